// round 13
// baseline (speedup 1.0000x reference)
#include <cuda_runtime.h>
#include <cuda_fp16.h>
#include <math.h>
#include <stdint.h>

#define B_ROWS 16384
#define DIMK   1024
#define N_EXP  8

// ---------------------------------------------------------------------------
// Static device scratch (no allocations allowed)
// ---------------------------------------------------------------------------
__device__ __half g_comb[(size_t)B_ROWS * DIMK];          // fp16 [m][k]
__device__ __half g_w1t[(size_t)N_EXP * DIMK * DIMK];     // [e][n][k] fp16
__device__ __half g_w2t[(size_t)N_EXP * DIMK * DIMK];
__device__ __half g_H[(size_t)N_EXP * B_ROWS * DIMK];     // [e][m][k] fp16
__device__ __half g_Yh[(size_t)N_EXP * B_ROWS * DIMK];    // [e][m][n] fp16
__device__ float  g_wts[(size_t)B_ROWS * N_EXP];

// ---------------------------------------------------------------------------
// helpers (sm_80-level PTX only)
// ---------------------------------------------------------------------------
__device__ __forceinline__ void cp16(uint32_t dst, const void* src) {
    asm volatile("cp.async.cg.shared.global [%0], [%1], 16;"
                 :: "r"(dst), "l"(__cvta_generic_to_global(src)) : "memory");
}
__device__ __forceinline__ void ldsm_x4(uint32_t* r, uint32_t addr) {
    asm volatile("ldmatrix.sync.aligned.m8n8.x4.shared.b16 {%0,%1,%2,%3}, [%4];"
                 : "=r"(r[0]), "=r"(r[1]), "=r"(r[2]), "=r"(r[3]) : "r"(addr));
}
__device__ __forceinline__ void mma_f16(float* d, const uint32_t* a, const uint32_t* b) {
    asm volatile("mma.sync.aligned.m16n8k16.row.col.f32.f16.f16.f32 "
                 "{%0,%1,%2,%3}, {%4,%5,%6,%7}, {%8,%9}, {%0,%1,%2,%3};"
                 : "+f"(d[0]), "+f"(d[1]), "+f"(d[2]), "+f"(d[3])
                 : "r"(a[0]), "r"(a[1]), "r"(a[2]), "r"(a[3]), "r"(b[0]), "r"(b[1]));
}
// swizzled byte offset within a [rows x 64 fp16] tile (128B rows, 8x16B chunks)
__device__ __forceinline__ uint32_t swz(int r, int c) {
    return (uint32_t)(r * 128 + ((c ^ (r & 7)) << 4));
}

// ---------------------------------------------------------------------------
// Input convert / weight transpose kernels
// ---------------------------------------------------------------------------
__global__ void conv_comb_kernel(const float* __restrict__ zs,
                                 const float* __restrict__ ze) {
    size_t g = (size_t)blockIdx.x * blockDim.x + threadIdx.x;
    if (g >= (size_t)B_ROWS * DIMK) return;
    size_t b = g >> 10; int i = (int)(g & 1023);
    float v = (i < 512) ? zs[(b << 9) + i] : ze[(b << 9) + i - 512];
    g_comb[g] = __float2half_rn(v);
}

// w: [e][k][n] fp32 -> out: [e][n][k] fp16; smem-tiled 64x64 transpose
__global__ void __launch_bounds__(256) split_wT_kernel(
    const float* __restrict__ w, __half* __restrict__ t)
{
    __shared__ float s[64][65];
    const int tid = threadIdx.x;
    const int tk = blockIdx.y * 64, tn = blockIdx.x * 64;
    const size_t eo = (size_t)blockIdx.z << 20;

#pragma unroll
    for (int i = 0; i < 16; i++) {
        int idx = tid + i * 256;
        int kk = idx >> 6, nn = idx & 63;
        s[kk][nn] = w[eo + (size_t)(tk + kk) * DIMK + tn + nn];
    }
    __syncthreads();
#pragma unroll
    for (int i = 0; i < 16; i++) {
        int idx = tid + i * 256;
        int nn = idx >> 6, kk = idx & 63;
        t[eo + (size_t)(tn + nn) * DIMK + tk + kk] = __float2half_rn(s[kk][nn]);
    }
}

// ---------------------------------------------------------------------------
// Router softmax: one row per warp
// ---------------------------------------------------------------------------
__global__ void __launch_bounds__(256) router_kernel(
    const float* __restrict__ zs, const float* __restrict__ ze,
    const float* __restrict__ rw, const float* __restrict__ rb)
{
    __shared__ float rws[N_EXP][DIMK];
    __shared__ float rbs[N_EXP];
    const int tid = threadIdx.x, lane = tid & 31, w = tid >> 5;

    for (int i = tid; i < N_EXP * DIMK; i += 256) {
        int k = i >> 3, e = i & 7;
        rws[e][k] = rw[i];
    }
    if (tid < N_EXP) rbs[tid] = rb[tid];
    __syncthreads();

    const int b = blockIdx.x * 8 + w;
    float acc[N_EXP];
#pragma unroll
    for (int e = 0; e < N_EXP; e++) acc[e] = 0.f;
#pragma unroll
    for (int j = 0; j < 32; j++) {
        int k = j * 32 + lane;
        float xv = (k < 512) ? zs[(size_t)b * 512 + k]
                             : ze[(size_t)b * 512 + k - 512];
#pragma unroll
        for (int e = 0; e < N_EXP; e++) acc[e] += xv * rws[e][k];
    }
#pragma unroll
    for (int e = 0; e < N_EXP; e++)
#pragma unroll
        for (int s = 16; s; s >>= 1)
            acc[e] += __shfl_xor_sync(0xffffffffu, acc[e], s);
    if (lane == 0) {
        float mx = -1e30f;
#pragma unroll
        for (int e = 0; e < N_EXP; e++) { acc[e] += rbs[e]; mx = fmaxf(mx, acc[e]); }
        float sum = 0.f;
#pragma unroll
        for (int e = 0; e < N_EXP; e++) { acc[e] = expf(acc[e] - mx); sum += acc[e]; }
        float inv = 1.f / sum;
#pragma unroll
        for (int e = 0; e < N_EXP; e++) g_wts[(size_t)b * N_EXP + e] = acc[e] * inv;
    }
}

// ---------------------------------------------------------------------------
// fp16 mma.sync GEMM, single term, CTA tile 256x128, BK=64, 3 stages,
// 8 warps (4x2), warp tile 64x64.
// mode 1: Oh = fp16(gelu(D+bias));  mode 0: Oh = fp16(D+bias)
// ---------------------------------------------------------------------------
#define BM       256
#define A_TILE_B (BM * 128)              // 256 rows x 128 B = 32 KB
#define B_TILE_B (128 * 128)             // 128 rows x 128 B = 16 KB
#define STAGE_B  (A_TILE_B + B_TILE_B)   // 48 KB
#define STAGES   3
#define SMEM_BYTES (STAGES * STAGE_B)    // 144 KB
#define CHUNKS   (DIMK / 64)             // 16

__device__ __forceinline__ void load_chunk(uint32_t stage_base,
                                           const __half* pA,
                                           const __half* pB,
                                           int k0, int tid) {
    // A: 256 rows x 8 chunks = 2048 cp16 over 256 threads -> 8 each
#pragma unroll
    for (int i = 0; i < 8; i++) {
        int id = tid + i * 256;          // 0..2047
        int r = id >> 3;                 // 0..255
        int c = id & 7;                  // 16B chunk
        cp16(stage_base + swz(r, c), pA + (size_t)r * DIMK + k0 + c * 8);
    }
    // B: 128 rows x 8 chunks = 1024 cp16 -> 4 each
#pragma unroll
    for (int i = 0; i < 4; i++) {
        int id = tid + i * 256;          // 0..1023
        int r = id >> 3;                 // 0..127
        int c = id & 7;
        cp16(stage_base + A_TILE_B + swz(r, c), pB + (size_t)r * DIMK + k0 + c * 8);
    }
}

__global__ void __launch_bounds__(256, 1) gemm_mma_kernel(
    const __half* __restrict__ A, size_t a_estride,
    const __half* __restrict__ Bw,
    const float* __restrict__ bias, int mode,
    __half* __restrict__ Oh)
{
    extern __shared__ char smem[];
    const int tid  = threadIdx.x;
    const int wid  = tid >> 5;
    const int lane = tid & 31;
    const int cb = blockIdx.x;
    const int rb = blockIdx.y;
    const int e  = blockIdx.z;
    const int wm = (wid >> 1) * 64;      // 0/64/128/192
    const int wn = (wid & 1) * 64;       // 0/64

    const uint32_t sbase = (uint32_t)__cvta_generic_to_shared(smem);

    const __half* pA = A + (size_t)e * a_estride + (size_t)rb * BM * DIMK;
    const __half* pB = Bw + ((size_t)e * DIMK + (size_t)cb * 128) * DIMK;

    float acc[4][8][4];
#pragma unroll
    for (int i = 0; i < 4; i++)
#pragma unroll
        for (int j = 0; j < 8; j++)
#pragma unroll
            for (int k = 0; k < 4; k++) acc[i][j][k] = 0.f;

#pragma unroll
    for (int s = 0; s < STAGES - 1; s++) {
        load_chunk(sbase + s * STAGE_B, pA, pB, s * 64, tid);
        asm volatile("cp.async.commit_group;" ::: "memory");
    }

    const int jA = lane >> 3;
    const int rA_base = ((jA & 1) << 3) + (lane & 7);
    const int cA_base = jA >> 1;
    const int jB = lane >> 3;
    const int rB_base = ((jB >> 1) << 3) + (lane & 7);
    const int cB_base = jB & 1;

    for (int c = 0; c < CHUNKS; c++) {
        const int pf = c + STAGES - 1;
        if (pf < CHUNKS) {
            asm volatile("cp.async.wait_group %0;" :: "n"(STAGES - 2) : "memory");
        } else {
            asm volatile("cp.async.wait_group 0;" ::: "memory");
        }
        __syncthreads();
        if (pf < CHUNKS) {
            load_chunk(sbase + (pf % STAGES) * STAGE_B, pA, pB, pf * 64, tid);
            asm volatile("cp.async.commit_group;" ::: "memory");
        }

        const uint32_t a_b = sbase + (c % STAGES) * STAGE_B;
        const uint32_t b_b = a_b + A_TILE_B;

#pragma unroll
        for (int ks = 0; ks < 4; ks++) {           // 4 k16-groups per 64-chunk
            const int kc0 = ks * 2;
            uint32_t bw[8][2];
#pragma unroll
            for (int q = 0; q < 4; q++) {
                int rB = wn + q * 16 + rB_base;
                int cB = kc0 + cB_base;
                uint32_t t[4];
                ldsm_x4(t, b_b + swz(rB, cB));
                bw[2 * q][0] = t[0]; bw[2 * q][1] = t[1];
                bw[2 * q + 1][0] = t[2]; bw[2 * q + 1][1] = t[3];
            }
#pragma unroll
            for (int mf = 0; mf < 4; mf++) {
                int rA = wm + mf * 16 + rA_base;
                int cA = kc0 + cA_base;
                uint32_t av[4];
                ldsm_x4(av, a_b + swz(rA, cA));
#pragma unroll
                for (int nf = 0; nf < 8; nf++)
                    mma_f16(acc[mf][nf], av, bw[nf]);
            }
        }
    }

    // --------------------------- epilogue ---------------------------
    const float* bias_e = bias + (size_t)e * DIMK;
#pragma unroll
    for (int mf = 0; mf < 4; mf++) {
#pragma unroll
        for (int nf = 0; nf < 8; nf++) {
#pragma unroll
            for (int h = 0; h < 2; h++) {
                int row = rb * BM + wm + mf * 16 + (lane >> 2) + h * 8;
                int col = cb * 128 + wn + nf * 8 + ((lane & 3) << 1);
                float v0 = acc[mf][nf][2 * h]     + bias_e[col];
                float v1 = acc[mf][nf][2 * h + 1] + bias_e[col + 1];
                size_t o = (size_t)e * ((size_t)B_ROWS * DIMK)
                         + (size_t)row * DIMK + col;
                if (mode) {
                    v0 = 0.5f * v0 * (1.0f + erff(v0 * 0.70710678118654752f));
                    v1 = 0.5f * v1 * (1.0f + erff(v1 * 0.70710678118654752f));
                }
                __half2 ph;
                ph.x = __float2half_rn(v0);
                ph.y = __float2half_rn(v1);
                *(__half2*)(Oh + o) = ph;
            }
        }
    }
}

// ---------------------------------------------------------------------------
// LayerNorm + combine: warp-per-expert, fp16 Y input, shfl reductions.
// ---------------------------------------------------------------------------
__global__ void __launch_bounds__(256) ln_combine_kernel(
    const float* __restrict__ gamma, const float* __restrict__ beta,
    float* __restrict__ out)
{
    __shared__ float ybuf[N_EXP][DIMK];
    const int b = blockIdx.x;
    const int tid = threadIdx.x;
    const int e = tid >> 5;
    const int lane = tid & 31;

    const uint4* y4 = (const uint4*)(g_Yh + ((size_t)e * B_ROWS + b) * DIMK);
    float v[32];
    float s = 0.f;
#pragma unroll
    for (int j = 0; j < 4; j++) {
        uint4 raw = y4[j * 32 + lane];
        const uint32_t wds[4] = {raw.x, raw.y, raw.z, raw.w};
#pragma unroll
        for (int q = 0; q < 4; q++) {
            __half2 h2 = *(const __half2*)&wds[q];
            float2 f = __half22float2(h2);
            v[j * 8 + q * 2]     = f.x;
            v[j * 8 + q * 2 + 1] = f.y;
            s += f.x + f.y;
        }
    }
#pragma unroll
    for (int st = 16; st; st >>= 1) s += __shfl_xor_sync(0xffffffffu, s, st);
    const float mu = s * (1.f / DIMK);

    float s2 = 0.f;
#pragma unroll
    for (int i = 0; i < 32; i++) {
        float d = v[i] - mu;
        s2 += d * d;
    }
#pragma unroll
    for (int st = 16; st; st >>= 1) s2 += __shfl_xor_sync(0xffffffffu, s2, st);
    const float inv = rsqrtf(s2 * (1.f / DIMK) + 1e-5f);
    const float wgt = g_wts[(size_t)b * N_EXP + e];

    const float4* g4 = (const float4*)(gamma + (size_t)e * DIMK);
    const float4* b4 = (const float4*)(beta + (size_t)e * DIMK);
#pragma unroll
    for (int j = 0; j < 4; j++) {
        int base4 = (j * 32 + lane) * 2;
#pragma unroll
        for (int hh = 0; hh < 2; hh++) {
            float4 gg = g4[base4 + hh], bb = b4[base4 + hh], r;
            int vi = j * 8 + hh * 4;
            r.x = wgt * ((v[vi]     - mu) * inv * gg.x + bb.x);
            r.y = wgt * ((v[vi + 1] - mu) * inv * gg.y + bb.y);
            r.z = wgt * ((v[vi + 2] - mu) * inv * gg.z + bb.z);
            r.w = wgt * ((v[vi + 3] - mu) * inv * gg.w + bb.w);
            *(float4*)&ybuf[e][(base4 + hh) * 4] = r;
        }
    }
    __syncthreads();

    float4 a = *(float4*)&ybuf[0][tid * 4];
#pragma unroll
    for (int ee = 1; ee < N_EXP; ee++) {
        float4 u = *(float4*)&ybuf[ee][tid * 4];
        a.x += u.x; a.y += u.y; a.z += u.z; a.w += u.w;
    }
    *(float4*)(out + (size_t)b * DIMK + tid * 4) = a;
}

// ---------------------------------------------------------------------------
// Host launch
// ---------------------------------------------------------------------------
extern "C" void kernel_launch(void* const* d_in, const int* in_sizes, int n_in,
                              void* d_out, int out_size)
{
    const float* z_s   = (const float*)d_in[0];
    const float* z_e   = (const float*)d_in[1];
    const float* rw    = (const float*)d_in[2];
    const float* rb    = (const float*)d_in[3];
    const float* w1    = (const float*)d_in[4];
    const float* b1    = (const float*)d_in[5];
    const float* w2    = (const float*)d_in[6];
    const float* b2    = (const float*)d_in[7];
    const float* gamma = (const float*)d_in[8];
    const float* beta  = (const float*)d_in[9];
    float* out = (float*)d_out;

    __half *comb, *w1t, *w2t, *H, *Yh;
    cudaGetSymbolAddress((void**)&comb, g_comb);
    cudaGetSymbolAddress((void**)&w1t, g_w1t);
    cudaGetSymbolAddress((void**)&w2t, g_w2t);
    cudaGetSymbolAddress((void**)&H, g_H);
    cudaGetSymbolAddress((void**)&Yh, g_Yh);

    cudaFuncSetAttribute(gemm_mma_kernel,
                         cudaFuncAttributeMaxDynamicSharedMemorySize, SMEM_BYTES);

    {
        size_t total = (size_t)B_ROWS * DIMK;
        conv_comb_kernel<<<(int)((total + 255) / 256), 256>>>(z_s, z_e);
    }
    {
        dim3 tg(16, 16, 8);
        split_wT_kernel<<<tg, 256>>>(w1, w1t);
        split_wT_kernel<<<tg, 256>>>(w2, w2t);
    }
    router_kernel<<<B_ROWS / 8, 256>>>(z_s, z_e, rw, rb);

    dim3 grid(8, B_ROWS / BM, 8);   // (8, 64, 8)
    // GEMM1: H = fp16(gelu(comb @ w1 + b1))
    gemm_mma_kernel<<<grid, 256, SMEM_BYTES>>>(
        comb, (size_t)0, w1t, b1, 1, H);
    // GEMM2: Yh = fp16(H @ w2 + b2)
    gemm_mma_kernel<<<grid, 256, SMEM_BYTES>>>(
        H, (size_t)B_ROWS * DIMK, w2t, b2, 0, Yh);

    ln_combine_kernel<<<B_ROWS, 256>>>(gamma, beta, out);
}

// round 15
// speedup vs baseline: 1.1303x; 1.1303x over previous
#include <cuda_runtime.h>
#include <cuda_fp16.h>
#include <math.h>
#include <stdint.h>

#define B_ROWS 16384
#define DIMK   1024
#define N_EXP  8

// ---------------------------------------------------------------------------
// Static device scratch (no allocations allowed)
// ---------------------------------------------------------------------------
__device__ __half g_comb[(size_t)B_ROWS * DIMK];          // fp16 [m][k]
__device__ __half g_w1t[(size_t)N_EXP * DIMK * DIMK];     // [e][n][k] fp16
__device__ __half g_w2t[(size_t)N_EXP * DIMK * DIMK];
__device__ __half g_H[(size_t)N_EXP * B_ROWS * DIMK];     // [e][m][k] fp16
__device__ __half g_Yh[(size_t)N_EXP * B_ROWS * DIMK];    // [e][m][n] fp16
__device__ float  g_wts[(size_t)B_ROWS * N_EXP];

// ---------------------------------------------------------------------------
// helpers (sm_80-level PTX only)
// ---------------------------------------------------------------------------
__device__ __forceinline__ void cp16(uint32_t dst, const void* src) {
    asm volatile("cp.async.cg.shared.global [%0], [%1], 16;"
                 :: "r"(dst), "l"(__cvta_generic_to_global(src)) : "memory");
}
__device__ __forceinline__ void ldsm_x4(uint32_t* r, uint32_t addr) {
    asm volatile("ldmatrix.sync.aligned.m8n8.x4.shared.b16 {%0,%1,%2,%3}, [%4];"
                 : "=r"(r[0]), "=r"(r[1]), "=r"(r[2]), "=r"(r[3]) : "r"(addr));
}
__device__ __forceinline__ void mma_f16(float* d, const uint32_t* a, const uint32_t* b) {
    asm volatile("mma.sync.aligned.m16n8k16.row.col.f32.f16.f16.f32 "
                 "{%0,%1,%2,%3}, {%4,%5,%6,%7}, {%8,%9}, {%0,%1,%2,%3};"
                 : "+f"(d[0]), "+f"(d[1]), "+f"(d[2]), "+f"(d[3])
                 : "r"(a[0]), "r"(a[1]), "r"(a[2]), "r"(a[3]), "r"(b[0]), "r"(b[1]));
}
// swizzled byte offset within a [128 rows x 64 fp16] tile (128B rows, 8x16B chunks)
__device__ __forceinline__ uint32_t swz(int r, int c) {
    return (uint32_t)(r * 128 + ((c ^ (r & 7)) << 4));
}

// ---------------------------------------------------------------------------
// Weight transpose: w [e][k][n] fp32 -> t [e][n][k] fp16
// ---------------------------------------------------------------------------
__global__ void __launch_bounds__(256) split_wT_kernel(
    const float* __restrict__ w, __half* __restrict__ t)
{
    __shared__ float s[64][65];
    const int tid = threadIdx.x;
    const int tk = blockIdx.y * 64, tn = blockIdx.x * 64;
    const size_t eo = (size_t)blockIdx.z << 20;

#pragma unroll
    for (int i = 0; i < 16; i++) {
        int idx = tid + i * 256;
        int kk = idx >> 6, nn = idx & 63;
        s[kk][nn] = w[eo + (size_t)(tk + kk) * DIMK + tn + nn];
    }
    __syncthreads();
#pragma unroll
    for (int i = 0; i < 16; i++) {
        int idx = tid + i * 256;
        int nn = idx >> 6, kk = idx & 63;
        t[eo + (size_t)(tn + nn) * DIMK + tk + kk] = __float2half_rn(s[kk][nn]);
    }
}

// ---------------------------------------------------------------------------
// Router softmax + fp16 concat (fused): one row per warp.
// Each warp computes softmax weights for its row AND writes g_comb fp16.
// ---------------------------------------------------------------------------
__global__ void __launch_bounds__(256) router_kernel(
    const float* __restrict__ zs, const float* __restrict__ ze,
    const float* __restrict__ rw, const float* __restrict__ rb)
{
    __shared__ float rws[N_EXP][DIMK];
    __shared__ float rbs[N_EXP];
    const int tid = threadIdx.x, lane = tid & 31, w = tid >> 5;

    for (int i = tid; i < N_EXP * DIMK; i += 256) {
        int k = i >> 3, e = i & 7;
        rws[e][k] = rw[i];
    }
    if (tid < N_EXP) rbs[tid] = rb[tid];
    __syncthreads();

    const int b = blockIdx.x * 8 + w;
    float acc[N_EXP];
#pragma unroll
    for (int e = 0; e < N_EXP; e++) acc[e] = 0.f;
#pragma unroll
    for (int j = 0; j < 32; j++) {
        int k = j * 32 + lane;
        float xv = (k < 512) ? zs[(size_t)b * 512 + k]
                             : ze[(size_t)b * 512 + k - 512];
        g_comb[(size_t)b * DIMK + k] = __float2half_rn(xv);   // fused concat
#pragma unroll
        for (int e = 0; e < N_EXP; e++) acc[e] += xv * rws[e][k];
    }
#pragma unroll
    for (int e = 0; e < N_EXP; e++)
#pragma unroll
        for (int s = 16; s; s >>= 1)
            acc[e] += __shfl_xor_sync(0xffffffffu, acc[e], s);
    if (lane == 0) {
        float mx = -1e30f;
#pragma unroll
        for (int e = 0; e < N_EXP; e++) { acc[e] += rbs[e]; mx = fmaxf(mx, acc[e]); }
        float sum = 0.f;
#pragma unroll
        for (int e = 0; e < N_EXP; e++) { acc[e] = expf(acc[e] - mx); sum += acc[e]; }
        float inv = 1.f / sum;
#pragma unroll
        for (int e = 0; e < N_EXP; e++) g_wts[(size_t)b * N_EXP + e] = acc[e] * inv;
    }
}

// ---------------------------------------------------------------------------
// fp16 mma.sync GEMM, single term, BK=64, 3 stages, 4 warps, warp tile 64x64.
// (R12 proven config; A-fragments batched per ks.)
// mode 1: Oh = fp16(gelu(D+bias));  mode 0: Oh = fp16(D+bias)
// ---------------------------------------------------------------------------
#define TILE_B   16384                   // 128 x 64 fp16
#define STAGE_B  (2 * TILE_B)            // A, B
#define STAGES   3
#define SMEM_BYTES (STAGES * STAGE_B)    // 96 KB
#define CHUNKS   (DIMK / 64)             // 16

__device__ __forceinline__ void load_chunk(uint32_t stage_base,
                                           const __half* pA,
                                           const __half* pB,
                                           int k0, int tid) {
#pragma unroll
    for (int i = 0; i < 8; i++) {
        int id = tid + i * 128;          // 0..1023
        int r = id >> 3;                 // 0..127
        int c = id & 7;                  // 16B chunk 0..7
        uint32_t o = swz(r, c);
        const size_t s = (size_t)r * DIMK + k0 + c * 8;
        cp16(stage_base + o,          pA + s);
        cp16(stage_base + TILE_B + o, pB + s);
    }
}

__global__ void __launch_bounds__(128, 2) gemm_mma_kernel(
    const __half* __restrict__ A, size_t a_estride,
    const __half* __restrict__ Bw,
    const float* __restrict__ bias, int mode,
    __half* __restrict__ Oh)
{
    extern __shared__ char smem[];
    const int tid  = threadIdx.x;
    const int wid  = tid >> 5;
    const int lane = tid & 31;
    const int cb = blockIdx.x;
    const int rb = blockIdx.y;
    const int e  = blockIdx.z;
    const int wm = (wid >> 1) * 64;
    const int wn = (wid & 1) * 64;

    const uint32_t sbase = (uint32_t)__cvta_generic_to_shared(smem);

    const __half* pA = A + (size_t)e * a_estride + (size_t)rb * 128 * DIMK;
    const __half* pB = Bw + ((size_t)e * DIMK + (size_t)cb * 128) * DIMK;

    float acc[4][8][4];
#pragma unroll
    for (int i = 0; i < 4; i++)
#pragma unroll
        for (int j = 0; j < 8; j++)
#pragma unroll
            for (int k = 0; k < 4; k++) acc[i][j][k] = 0.f;

#pragma unroll
    for (int s = 0; s < STAGES - 1; s++) {
        load_chunk(sbase + s * STAGE_B, pA, pB, s * 64, tid);
        asm volatile("cp.async.commit_group;" ::: "memory");
    }

    const int jA = lane >> 3;
    const int rA_base = ((jA & 1) << 3) + (lane & 7);
    const int cA_base = jA >> 1;
    const int jB = lane >> 3;
    const int rB_base = ((jB >> 1) << 3) + (lane & 7);
    const int cB_base = jB & 1;

    for (int c = 0; c < CHUNKS; c++) {
        const int pf = c + STAGES - 1;
        if (pf < CHUNKS) {
            asm volatile("cp.async.wait_group %0;" :: "n"(STAGES - 2) : "memory");
        } else {
            asm volatile("cp.async.wait_group 0;" ::: "memory");
        }
        __syncthreads();
        if (pf < CHUNKS) {
            load_chunk(sbase + (pf % STAGES) * STAGE_B, pA, pB, pf * 64, tid);
            asm volatile("cp.async.commit_group;" ::: "memory");
        }

        const uint32_t a_b = sbase + (c % STAGES) * STAGE_B;
        const uint32_t b_b = a_b + TILE_B;

#pragma unroll
        for (int ks = 0; ks < 4; ks++) {           // 4 k16-groups per 64-chunk
            const int kc0 = ks * 2;
            uint32_t bw[8][2];
#pragma unroll
            for (int q = 0; q < 4; q++) {
                int rB = wn + q * 16 + rB_base;
                int cB = kc0 + cB_base;
                uint32_t t[4];
                ldsm_x4(t, b_b + swz(rB, cB));
                bw[2 * q][0] = t[0]; bw[2 * q][1] = t[1];
                bw[2 * q + 1][0] = t[2]; bw[2 * q + 1][1] = t[3];
            }
            // batch all A fragments for this ks, then issue all MMAs
            uint32_t av[4][4];
#pragma unroll
            for (int mf = 0; mf < 4; mf++) {
                int rA = wm + mf * 16 + rA_base;
                int cA = kc0 + cA_base;
                ldsm_x4(av[mf], a_b + swz(rA, cA));
            }
#pragma unroll
            for (int mf = 0; mf < 4; mf++)
#pragma unroll
                for (int nf = 0; nf < 8; nf++)
                    mma_f16(acc[mf][nf], av[mf], bw[nf]);
        }
    }

    // --------------------------- epilogue ---------------------------
    const float* bias_e = bias + (size_t)e * DIMK;
#pragma unroll
    for (int mf = 0; mf < 4; mf++) {
#pragma unroll
        for (int nf = 0; nf < 8; nf++) {
#pragma unroll
            for (int h = 0; h < 2; h++) {
                int row = rb * 128 + wm + mf * 16 + (lane >> 2) + h * 8;
                int col = cb * 128 + wn + nf * 8 + ((lane & 3) << 1);
                float v0 = acc[mf][nf][2 * h]     + bias_e[col];
                float v1 = acc[mf][nf][2 * h + 1] + bias_e[col + 1];
                size_t o = (size_t)e * ((size_t)B_ROWS * DIMK)
                         + (size_t)row * DIMK + col;
                if (mode) {
                    v0 = 0.5f * v0 * (1.0f + erff(v0 * 0.70710678118654752f));
                    v1 = 0.5f * v1 * (1.0f + erff(v1 * 0.70710678118654752f));
                }
                __half2 ph;
                ph.x = __float2half_rn(v0);
                ph.y = __float2half_rn(v1);
                *(__half2*)(Oh + o) = ph;
            }
        }
    }
}

// ---------------------------------------------------------------------------
// LayerNorm + combine: warp-per-expert, fp16 Y input, shfl reductions.
// ---------------------------------------------------------------------------
__global__ void __launch_bounds__(256) ln_combine_kernel(
    const float* __restrict__ gamma, const float* __restrict__ beta,
    float* __restrict__ out)
{
    __shared__ float ybuf[N_EXP][DIMK];
    const int b = blockIdx.x;
    const int tid = threadIdx.x;
    const int e = tid >> 5;
    const int lane = tid & 31;

    const uint4* y4 = (const uint4*)(g_Yh + ((size_t)e * B_ROWS + b) * DIMK);
    float v[32];
    float s = 0.f;
#pragma unroll
    for (int j = 0; j < 4; j++) {
        uint4 raw = y4[j * 32 + lane];
        const uint32_t wds[4] = {raw.x, raw.y, raw.z, raw.w};
#pragma unroll
        for (int q = 0; q < 4; q++) {
            __half2 h2 = *(const __half2*)&wds[q];
            float2 f = __half22float2(h2);
            v[j * 8 + q * 2]     = f.x;
            v[j * 8 + q * 2 + 1] = f.y;
            s += f.x + f.y;
        }
    }
#pragma unroll
    for (int st = 16; st; st >>= 1) s += __shfl_xor_sync(0xffffffffu, s, st);
    const float mu = s * (1.f / DIMK);

    float s2 = 0.f;
#pragma unroll
    for (int i = 0; i < 32; i++) {
        float d = v[i] - mu;
        s2 += d * d;
    }
#pragma unroll
    for (int st = 16; st; st >>= 1) s2 += __shfl_xor_sync(0xffffffffu, s2, st);
    const float inv = rsqrtf(s2 * (1.f / DIMK) + 1e-5f);
    const float wgt = g_wts[(size_t)b * N_EXP + e];

    const float4* g4 = (const float4*)(gamma + (size_t)e * DIMK);
    const float4* b4 = (const float4*)(beta + (size_t)e * DIMK);
#pragma unroll
    for (int j = 0; j < 4; j++) {
        int base4 = (j * 32 + lane) * 2;
#pragma unroll
        for (int hh = 0; hh < 2; hh++) {
            float4 gg = g4[base4 + hh], bb = b4[base4 + hh], r;
            int vi = j * 8 + hh * 4;
            r.x = wgt * ((v[vi]     - mu) * inv * gg.x + bb.x);
            r.y = wgt * ((v[vi + 1] - mu) * inv * gg.y + bb.y);
            r.z = wgt * ((v[vi + 2] - mu) * inv * gg.z + bb.z);
            r.w = wgt * ((v[vi + 3] - mu) * inv * gg.w + bb.w);
            *(float4*)&ybuf[e][(base4 + hh) * 4] = r;
        }
    }
    __syncthreads();

    float4 a = *(float4*)&ybuf[0][tid * 4];
#pragma unroll
    for (int ee = 1; ee < N_EXP; ee++) {
        float4 u = *(float4*)&ybuf[ee][tid * 4];
        a.x += u.x; a.y += u.y; a.z += u.z; a.w += u.w;
    }
    *(float4*)(out + (size_t)b * DIMK + tid * 4) = a;
}

// ---------------------------------------------------------------------------
// Host launch
// ---------------------------------------------------------------------------
extern "C" void kernel_launch(void* const* d_in, const int* in_sizes, int n_in,
                              void* d_out, int out_size)
{
    const float* z_s   = (const float*)d_in[0];
    const float* z_e   = (const float*)d_in[1];
    const float* rw    = (const float*)d_in[2];
    const float* rb    = (const float*)d_in[3];
    const float* w1    = (const float*)d_in[4];
    const float* b1    = (const float*)d_in[5];
    const float* w2    = (const float*)d_in[6];
    const float* b2    = (const float*)d_in[7];
    const float* gamma = (const float*)d_in[8];
    const float* beta  = (const float*)d_in[9];
    float* out = (float*)d_out;

    __half *comb, *w1t, *w2t, *H, *Yh;
    cudaGetSymbolAddress((void**)&comb, g_comb);
    cudaGetSymbolAddress((void**)&w1t, g_w1t);
    cudaGetSymbolAddress((void**)&w2t, g_w2t);
    cudaGetSymbolAddress((void**)&H, g_H);
    cudaGetSymbolAddress((void**)&Yh, g_Yh);

    cudaFuncSetAttribute(gemm_mma_kernel,
                         cudaFuncAttributeMaxDynamicSharedMemorySize, SMEM_BYTES);

    {
        dim3 tg(16, 16, 8);
        split_wT_kernel<<<tg, 256>>>(w1, w1t);
        split_wT_kernel<<<tg, 256>>>(w2, w2t);
    }
    router_kernel<<<B_ROWS / 8, 256>>>(z_s, z_e, rw, rb);   // also writes g_comb

    dim3 grid(8, 128, 8);
    // GEMM1: H = fp16(gelu(comb @ w1 + b1))
    gemm_mma_kernel<<<grid, 128, SMEM_BYTES>>>(
        comb, (size_t)0, w1t, b1, 1, H);
    // GEMM2: Yh = fp16(H @ w2 + b2)
    gemm_mma_kernel<<<grid, 128, SMEM_BYTES>>>(
        H, (size_t)B_ROWS * DIMK, w2t, b2, 0, Yh);

    ln_combine_kernel<<<B_ROWS, 256>>>(gamma, beta, out);
}